// round 11
// baseline (speedup 1.0000x reference)
#include <cuda_runtime.h>
#include <cstdint>

// Shift_7292854469289  — out[b,c,h,w] = x[b,c, srcH[h], srcW[w]]
// srcH[h] = clamp(h + trunc(ypos[h]*stride), 0, H-1)
// srcW[w] = clamp(w + trunc(xpos[w]*stride), 0, W-1)
// B=16, C=64, H=W=256, fp32. HBM-roofline gather (~394MB @ ~6TB/s measured).
// R11: 256-bit loads (sm_10x LDG.256) — each thread owns 8 consecutive w,
//      BC_PER=4 planes. Last untested axis: access width 16B -> 32B.

#define H_ 256
#define W_ 256
#define W4_ 64                 // W/4 (float4 units per row)
#define W8_ 32                 // W/8 (float8 groups per row)
#define IMG4 (H_ * W4_)        // float4 elements per (b,c) plane
#define BC_PER 4               // bc planes per thread (measured optimum)

struct U8 { unsigned int r[8]; };

__device__ __forceinline__ U8 ldg256(const float4* p) {
    U8 v;
    asm volatile("ld.global.nc.v8.b32 {%0,%1,%2,%3,%4,%5,%6,%7}, [%8];"
                 : "=r"(v.r[0]), "=r"(v.r[1]), "=r"(v.r[2]), "=r"(v.r[3]),
                   "=r"(v.r[4]), "=r"(v.r[5]), "=r"(v.r[6]), "=r"(v.r[7])
                 : "l"(p));
    return v;
}
__device__ __forceinline__ void st128x2(float4* p, const U8& v) {
    asm volatile("st.global.v4.b32 [%0], {%1,%2,%3,%4};"
                 :: "l"(p), "r"(v.r[0]), "r"(v.r[1]), "r"(v.r[2]), "r"(v.r[3])
                 : "memory");
    asm volatile("st.global.v4.b32 [%0], {%1,%2,%3,%4};"
                 :: "l"(p + 1), "r"(v.r[4]), "r"(v.r[5]), "r"(v.r[6]), "r"(v.r[7])
                 : "memory");
}

__global__ void __launch_bounds__(256) shift_w8_kernel(
    const float4* __restrict__ x4,
    const float4* __restrict__ xpos4,
    const float*  __restrict__ ypos,
    const int*    __restrict__ stride_p,
    float4*       __restrict__ out4)
{
    unsigned int tid = blockIdx.x * 256u + threadIdx.x; // 256(bcg) x 256(h) x 32(w8)
    int w8  = tid & 31;
    int h   = (tid >> 5) & 255;
    unsigned int bcg = tid >> 13;               // 0..255
    unsigned int bc0 = bcg * BC_PER;

    const int stride = *stride_p;

    // ---- index math entirely in registers ----
    // trunc toward zero == C float->int cast (matches Python int())
    int srcH = min(max(h + (int)(ypos[h] * (float)stride), 0), H_ - 1);

    float4 xpa = __ldg(xpos4 + 2 * w8);         // xpos[8w8 .. 8w8+3]
    float4 xpb = __ldg(xpos4 + 2 * w8 + 1);     // xpos[8w8+4 .. 8w8+7]
    int w0 = w8 << 3;
    int sw[8];
    sw[0] = min(max(w0     + (int)(xpa.x * (float)stride), 0), W_ - 1);
    sw[1] = min(max(w0 + 1 + (int)(xpa.y * (float)stride), 0), W_ - 1);
    sw[2] = min(max(w0 + 2 + (int)(xpa.z * (float)stride), 0), W_ - 1);
    sw[3] = min(max(w0 + 3 + (int)(xpa.w * (float)stride), 0), W_ - 1);
    sw[4] = min(max(w0 + 4 + (int)(xpb.x * (float)stride), 0), W_ - 1);
    sw[5] = min(max(w0 + 5 + (int)(xpb.y * (float)stride), 0), W_ - 1);
    sw[6] = min(max(w0 + 6 + (int)(xpb.z * (float)stride), 0), W_ - 1);
    sw[7] = min(max(w0 + 7 + (int)(xpb.w * (float)stride), 0), W_ - 1);

    bool vec = ((sw[0] & 7) == 0);
    #pragma unroll
    for (int i = 1; i < 8; i++) vec &= (sw[i] == sw[0] + i);

    size_t in_row  = (size_t)srcH * W4_;
    size_t out_idx = (size_t)bc0 * IMG4 + (size_t)h * W4_ + 2 * w8;

    if (vec) {
        // 32B-aligned (sw[0]%8==0, base 256B-aligned) -> LDG.256
        size_t in_idx = (size_t)bc0 * IMG4 + in_row + (sw[0] >> 2);
        U8 v0 = ldg256(x4 + in_idx);
        U8 v1 = ldg256(x4 + in_idx + IMG4);
        U8 v2 = ldg256(x4 + in_idx + 2 * IMG4);
        U8 v3 = ldg256(x4 + in_idx + 3 * IMG4);
        st128x2(out4 + out_idx,            v0);
        st128x2(out4 + out_idx + IMG4,     v1);
        st128x2(out4 + out_idx + 2 * IMG4, v2);
        st128x2(out4 + out_idx + 3 * IMG4, v3);
    } else {
        const float* xf = (const float*)x4;
        #pragma unroll
        for (int i = 0; i < BC_PER; i++) {
            const float* row = xf + ((size_t)(bc0 + i) * IMG4 + in_row) * 4;
            float4 va, vb;
            va.x = __ldg(row + sw[0]);
            va.y = __ldg(row + sw[1]);
            va.z = __ldg(row + sw[2]);
            va.w = __ldg(row + sw[3]);
            vb.x = __ldg(row + sw[4]);
            vb.y = __ldg(row + sw[5]);
            vb.z = __ldg(row + sw[6]);
            vb.w = __ldg(row + sw[7]);
            out4[out_idx + (size_t)i * IMG4]     = va;
            out4[out_idx + (size_t)i * IMG4 + 1] = vb;
        }
    }
}

// Generic fallback (any H, W): one thread per element.
__global__ void shift_kernel_generic(
    const float* __restrict__ x,
    const float* __restrict__ xpos,
    const float* __restrict__ ypos,
    const int*   __restrict__ stride_p,
    float*       __restrict__ out,
    int H, int W, long long total)
{
    const int stride = *stride_p;
    long long i = (long long)blockIdx.x * blockDim.x + threadIdx.x;
    if (i >= total) return;
    int w = (int)(i % W);
    long long r = i / W;
    int h = (int)(r % H);
    long long bc = r / H;

    int srcH = min(max(h + (int)(ypos[h] * (float)stride), 0), H - 1);
    int srcW = min(max(w + (int)(xpos[w] * (float)stride), 0), W - 1);
    out[i] = x[(bc * H + srcH) * (long long)W + srcW];
}

extern "C" void kernel_launch(void* const* d_in, const int* in_sizes, int n_in,
                              void* d_out, int out_size)
{
    const float* x      = (const float*)d_in[0];
    const float* xpos   = (const float*)d_in[1];
    const float* ypos   = (const float*)d_in[2];
    const int*   stride = (const int*)d_in[3];
    float* out = (float*)d_out;

    int W = in_sizes[1];   // xpos has W elements
    int H = in_sizes[2];   // ypos has H elements

    long long total = out_size;
    long long bc_total = total / ((long long)H * W);   // B*C

    if (H == 256 && W == 256 && bc_total == 1024 &&
        ((((uintptr_t)x) & 31) == 0) && ((((uintptr_t)out) & 31) == 0) &&
        ((((uintptr_t)xpos) & 15) == 0)) {
        // threads = (1024/4 bcg) * 256 h * 32 w8 = 2,097,152 -> 8192 blocks
        shift_w8_kernel<<<8192, 256>>>((const float4*)x, (const float4*)xpos,
                                       ypos, stride, (float4*)out);
    } else {
        int threads = 256;
        long long blocks = (total + threads - 1) / threads;
        shift_kernel_generic<<<(unsigned int)blocks, threads>>>(
            x, xpos, ypos, stride, out, H, W, total);
    }
}

// round 12
// speedup vs baseline: 1.1314x; 1.1314x over previous
#include <cuda_runtime.h>
#include <cstdint>

// Shift_7292854469289  — out[b,c,h,w] = x[b,c, srcH[h], srcW[w]]
// srcH[h] = clamp(h + trunc(ypos[h]*stride), 0, H-1)
// srcW[w] = clamp(w + trunc(xpos[w]*stride), 0, W-1)
// B=16, C=64, H=W=256, fp32.
// FINAL (R6 config, session best 70.1us total / 65.5us kernel):
//   register-only index math, BC_PER=4, 16B/lane loads+stores, plain STG.
// The kernel is at the effective mixed r/w HBM ceiling: ~394MB real traffic
// (268MB compulsory write + ~126MB L2-deduped read) @ ~6.0 TB/s = 65.4us.
// Verified invariant to: occupancy (63-87%), smem vs reg tables, store policy
// (stcs/plain), L2 evict hints, burst length (BC 2/4/8/16), width (4/16/32B).

#define H_ 256
#define W_ 256
#define W4_ 64                 // W/4
#define IMG4 (H_ * W4_)        // float4 elements per (b,c) plane
#define BC_PER 4               // bc planes per thread (measured optimum)

__global__ void __launch_bounds__(256) shift_reg4_kernel(
    const float4* __restrict__ x4,
    const float4* __restrict__ xpos4,
    const float*  __restrict__ ypos,
    const int*    __restrict__ stride_p,
    float4*       __restrict__ out4)
{
    unsigned int tid = blockIdx.x * 256u + threadIdx.x; // 256(bcg) x 256(h) x 64(w4)
    int w4  = tid & 63;
    int h   = (tid >> 6) & 255;
    unsigned int bcg = tid >> 14;               // 0..255
    unsigned int bc0 = bcg * BC_PER;

    const int stride = *stride_p;               // L2/L1-resident scalar

    // ---- index math entirely in registers ----
    // trunc toward zero == C float->int cast (matches Python int())
    int srcH = min(max(h + (int)(ypos[h] * (float)stride), 0), H_ - 1);

    float4 xp = __ldg(xpos4 + w4);              // xpos[4w4 .. 4w4+3]
    int w0  = w4 << 2;
    int sw0 = min(max(w0     + (int)(xp.x * (float)stride), 0), W_ - 1);
    int sw1 = min(max(w0 + 1 + (int)(xp.y * (float)stride), 0), W_ - 1);
    int sw2 = min(max(w0 + 2 + (int)(xp.z * (float)stride), 0), W_ - 1);
    int sw3 = min(max(w0 + 3 + (int)(xp.w * (float)stride), 0), W_ - 1);

    bool vec = ((sw0 & 3) == 0) & (sw1 == sw0 + 1) & (sw2 == sw0 + 2)
                                & (sw3 == sw0 + 3);

    size_t in_row  = (size_t)srcH * W4_;
    size_t out_idx = (size_t)bc0 * IMG4 + (size_t)h * W4_ + w4;

    if (vec) {
        size_t in_idx = (size_t)bc0 * IMG4 + in_row + (sw0 >> 2);
        float4 v0 = __ldg(x4 + in_idx);
        float4 v1 = __ldg(x4 + in_idx + IMG4);
        float4 v2 = __ldg(x4 + in_idx + 2 * IMG4);
        float4 v3 = __ldg(x4 + in_idx + 3 * IMG4);
        out4[out_idx]            = v0;
        out4[out_idx + IMG4]     = v1;
        out4[out_idx + 2 * IMG4] = v2;
        out4[out_idx + 3 * IMG4] = v3;
    } else {
        const float* xf = (const float*)x4;
        #pragma unroll
        for (int i = 0; i < BC_PER; i++) {
            const float* row = xf + ((size_t)(bc0 + i) * IMG4 + in_row) * 4;
            float4 v;
            v.x = __ldg(row + sw0);
            v.y = __ldg(row + sw1);
            v.z = __ldg(row + sw2);
            v.w = __ldg(row + sw3);
            out4[out_idx + (size_t)i * IMG4] = v;
        }
    }
}

// Generic fallback (any H, W): one thread per element.
__global__ void shift_kernel_generic(
    const float* __restrict__ x,
    const float* __restrict__ xpos,
    const float* __restrict__ ypos,
    const int*   __restrict__ stride_p,
    float*       __restrict__ out,
    int H, int W, long long total)
{
    const int stride = *stride_p;
    long long i = (long long)blockIdx.x * blockDim.x + threadIdx.x;
    if (i >= total) return;
    int w = (int)(i % W);
    long long r = i / W;
    int h = (int)(r % H);
    long long bc = r / H;

    int srcH = min(max(h + (int)(ypos[h] * (float)stride), 0), H - 1);
    int srcW = min(max(w + (int)(xpos[w] * (float)stride), 0), W - 1);
    out[i] = x[(bc * H + srcH) * (long long)W + srcW];
}

extern "C" void kernel_launch(void* const* d_in, const int* in_sizes, int n_in,
                              void* d_out, int out_size)
{
    const float* x      = (const float*)d_in[0];
    const float* xpos   = (const float*)d_in[1];
    const float* ypos   = (const float*)d_in[2];
    const int*   stride = (const int*)d_in[3];
    float* out = (float*)d_out;

    int W = in_sizes[1];   // xpos has W elements
    int H = in_sizes[2];   // ypos has H elements

    long long total = out_size;
    long long bc_total = total / ((long long)H * W);   // B*C

    if (H == 256 && W == 256 && bc_total == 1024 &&
        ((((uintptr_t)xpos) & 15) == 0)) {
        // threads = (1024/4 bc groups) * 256 h * 64 w4 = 4,194,304 -> 16384 blocks
        shift_reg4_kernel<<<16384, 256>>>((const float4*)x, (const float4*)xpos,
                                          ypos, stride, (float4*)out);
    } else {
        int threads = 256;
        long long blocks = (total + threads - 1) / threads;
        shift_kernel_generic<<<(unsigned int)blocks, threads>>>(
            x, xpos, ypos, stride, out, H, W, total);
    }
}